// round 14
// baseline (speedup 1.0000x reference)
#include <cuda_runtime.h>
#include <cstdint>
#include <cstddef>

#define FULLMASK 0xffffffffu

constexpr int B_   = 4;
constexpr int N_   = 8192;
constexpr int CIN  = 128;
constexpr int COUT = 256;
constexpr int KNNK = 32;
constexpr int NW   = 4;
constexpr int ROWS = B_ * N_;          // 32768
constexpr int KDIM = NW * CIN;         // 512
constexpr int QPW  = 4;                // queries per warp (selection)

// ---------------- scratch ----------------
__device__ float4 g_xyzw[ROWS];
__device__ int    g_knn[(size_t)ROWS * KNNK];   // sorted neighbor indices per query
__device__ float  g_feats[(size_t)ROWS * CIN];
__device__ float  g_aw[ROWS * NW];
__device__ float  g_parts[512 * COUT];
__device__ float  g_partq[512 * COUT];
__device__ float  g_scale[COUT];
__device__ float  g_shift[COUT];

// ---------------- helpers ----------------
static __device__ __forceinline__ float wsum(float v) {
    #pragma unroll
    for (int o = 16; o > 0; o >>= 1) v += __shfl_xor_sync(FULLMASK, v, o);
    return v;
}

static __device__ __forceinline__ float tf32r(float x) {
    uint32_t u;
    asm("cvt.rna.tf32.f32 %0, %1;" : "=r"(u) : "f"(x));
    return __uint_as_float(u);
}

static __device__ __forceinline__ void mma_tf32(float c[4], const uint32_t a[4],
                                                const uint32_t b[2]) {
    asm volatile(
        "mma.sync.aligned.m16n8k8.row.col.f32.tf32.tf32.f32 "
        "{%0,%1,%2,%3}, {%4,%5,%6,%7}, {%8,%9}, {%0,%1,%2,%3};\n"
        : "+f"(c[0]), "+f"(c[1]), "+f"(c[2]), "+f"(c[3])
        : "r"(a[0]), "r"(a[1]), "r"(a[2]), "r"(a[3]), "r"(b[0]), "r"(b[1]));
}

// lex compare helper: (pd,pi) < (d,i)
static __device__ __forceinline__ bool lex_less(float pd, int pi, float d, int i) {
    return (pd < d) || ((pd == d) && (pi < i));
}

// full bitonic sort of 32 (d,i) pairs across lanes, ascending lex
static __device__ __forceinline__ void bitonic_sort32(float& d, int& i, int lane) {
    #pragma unroll
    for (int k = 2; k <= 32; k <<= 1) {
        #pragma unroll
        for (int j = k >> 1; j > 0; j >>= 1) {
            float pd = __shfl_xor_sync(FULLMASK, d, j);
            int   pi = __shfl_xor_sync(FULLMASK, i, j);
            bool up      = ((lane & k) == 0);
            bool lower   = ((lane & j) == 0);
            bool wantMin = (lower == up);
            bool oLess   = lex_less(pd, pi, d, i);
            if (wantMin == oLess) { d = pd; i = pi; }
        }
    }
}

// bitonic merge (clean) of a bitonic 32-sequence -> ascending lex
static __device__ __forceinline__ void bitonic_clean32(float& d, int& i, int lane) {
    #pragma unroll
    for (int j = 16; j > 0; j >>= 1) {
        float pd = __shfl_xor_sync(FULLMASK, d, j);
        int   pi = __shfl_xor_sync(FULLMASK, i, j);
        bool wantMin = ((lane & j) == 0);
        bool oLess   = lex_less(pd, pi, d, i);
        if (wantMin == oLess) { d = pd; i = pi; }
    }
}

// ---------------- 1) pack xyz + squared norm (CERTIFIED — do not modify) --------
// sq = fma(x,x, fma(y,y, rn(z*z)))
__global__ void prep_kernel(const float* __restrict__ xyz) {
    int gid = blockIdx.x * blockDim.x + threadIdx.x;
    if (gid >= ROWS) return;
    float x = xyz[gid * 3 + 0];
    float y = xyz[gid * 3 + 1];
    float z = xyz[gid * 3 + 2];
    float sq = __fmaf_rn(x, x, __fmaf_rn(y, y, __fmul_rn(z, z)));
    g_xyzw[gid] = make_float4(x, y, z, sq);
}

// ---------------- 2a) KNN selection (QPW queries/warp) ---------------------------
// Output per query: the 32 lex-smallest (dist, idx) pairs, ascending == the
// certified stable-low top-k. Distance arithmetic is the certified chain.
__global__ void __launch_bounds__(256) knn_select(const float* __restrict__ dummy)
{
    int gw   = (blockIdx.x * blockDim.x + threadIdx.x) >> 5;
    int lane = threadIdx.x & 31;
    int wq   = gw * QPW;
    if (wq >= ROWS) return;
    int b = wq >> 13;

    const float4* cand = g_xyzw + (size_t)b * N_;
    int qbase = wq & (N_ - 1);

    float qx[QPW], qy[QPW], qz[QPW], qs[QPW];
    #pragma unroll
    for (int j = 0; j < QPW; ++j) {
        float4 s = __ldg(&cand[qbase + j]);
        qx[j] = s.x; qy[j] = s.y; qz[j] = s.z; qs[j] = s.w;
    }

    const float INF = __int_as_float(0x7f800000);
    float ld[QPW];
    int   li[QPW];
    float tau[QPW];

    // ---- chunk 0: direct bitonic sort of first 32 candidates ----
    {
        float4 c = __ldg(&cand[lane]);
        #pragma unroll
        for (int j = 0; j < QPW; ++j) {
            // CERTIFIED distance
            float dot = __fmul_rn(qx[j], c.x);
            dot = __fmaf_rn(qy[j], c.y, dot);
            dot = __fmaf_rn(qz[j], c.z, dot);
            float d = __fadd_rn(__fadd_rn(__fmul_rn(-2.0f, dot), qs[j]), c.w);
            float sd = d; int si = lane;
            bitonic_sort32(sd, si, lane);
            ld[j] = sd; li[j] = si;
            tau[j] = __shfl_sync(FULLMASK, sd, 31);
        }
    }

    // ---- remaining chunks ----
    #pragma unroll 2
    for (int base = 32; base < N_; base += 32) {
        float4 c = __ldg(&cand[base + lane]);
        float d[QPW];
        #pragma unroll
        for (int j = 0; j < QPW; ++j) {
            float dot = __fmul_rn(qx[j], c.x);
            dot = __fmaf_rn(qy[j], c.y, dot);
            dot = __fmaf_rn(qz[j], c.z, dot);
            d[j] = __fadd_rn(__fadd_rn(__fmul_rn(-2.0f, dot), qs[j]), c.w);
        }
        bool hit = (d[0] < tau[0]) | (d[1] < tau[1]) | (d[2] < tau[2]) | (d[3] < tau[3]);
        if (__ballot_sync(FULLMASK, hit)) {
            #pragma unroll
            for (int j = 0; j < QPW; ++j) {
                unsigned m = __ballot_sync(FULLMASK, d[j] < tau[j]);
                int h = __popc(m);
                if (h == 0) continue;
                if (h >= 6) {
                    // batch: sort hits, merge with list, keep lowest 32
                    bool v = d[j] < tau[j];
                    float sd = v ? d[j] : INF;
                    int   si = v ? (base + lane) : 0x7fffffff;
                    bitonic_sort32(sd, si, lane);
                    float rd = __shfl_xor_sync(FULLMASK, sd, 31);   // reverse
                    int   ri = __shfl_xor_sync(FULLMASK, si, 31);
                    if (lex_less(rd, ri, ld[j], li[j])) { ld[j] = rd; li[j] = ri; }
                    bitonic_clean32(ld[j], li[j], lane);
                    tau[j] = __shfl_sync(FULLMASK, ld[j], 31);
                } else {
                    // certified serial insertion
                    while (m) {
                        int src = __ffs(m) - 1;
                        m &= m - 1;
                        float dc = __shfl_sync(FULLMASK, d[j], src);
                        if (dc < tau[j]) {
                            int ic = base + src;
                            unsigned le = __ballot_sync(FULLMASK, ld[j] <= dc);
                            int pos = __popc(le);
                            float pd = __shfl_up_sync(FULLMASK, ld[j], 1);
                            int   pi = __shfl_up_sync(FULLMASK, li[j], 1);
                            if (lane == pos)      { ld[j] = dc; li[j] = ic; }
                            else if (lane > pos)  { ld[j] = pd; li[j] = pi; }
                            tau[j] = __shfl_sync(FULLMASK, ld[j], 31);
                        }
                    }
                }
            }
        }
    }

    #pragma unroll
    for (int j = 0; j < QPW; ++j)
        g_knn[(size_t)(wq + j) * KNNK + lane] = li[j];
}

// ---------------- 2b) KNN epilogue: one warp per query ---------------------------
// Identical arithmetic to certified epilogue; li read from g_knn (sorted order).
__global__ void __launch_bounds__(256) knn_epilogue(
    const float* __restrict__ points,
    const float* __restrict__ W1, const float* __restrict__ b1,
    const float* __restrict__ W2, const float* __restrict__ b2)
{
    int q    = (blockIdx.x * blockDim.x + threadIdx.x) >> 5;
    int lane = threadIdx.x & 31;
    if (q >= ROWS) return;
    int b = q >> 13;

    const float4* cand = g_xyzw + (size_t)b * N_;
    float4 self = __ldg(&cand[q & (N_ - 1)]);
    int li = g_knn[(size_t)q * KNNK + lane];
    float4 nb = __ldg(&cand[li]);

    float gx = wsum(__fadd_rn(nb.x, -self.x)) * (1.0f / 32.0f);
    float gy = wsum(__fadd_rn(nb.y, -self.y)) * (1.0f / 32.0f);
    float gz = wsum(__fadd_rn(nb.z, -self.z)) * (1.0f / 32.0f);

    float a0 = 0.f, a1 = 0.f, a2 = 0.f, a3 = 0.f;
    #pragma unroll
    for (int t = 0; t < 2; ++t) {
        int jj = lane + t * 32;
        float h = __ldg(&b1[jj]);
        h = __fmaf_rn(gx, __ldg(&W1[jj]),        h);
        h = __fmaf_rn(gy, __ldg(&W1[64 + jj]),   h);
        h = __fmaf_rn(gz, __ldg(&W1[128 + jj]),  h);
        h = fmaxf(h, 0.0f);
        a0 = __fmaf_rn(h, __ldg(&W2[jj * 4 + 0]), a0);
        a1 = __fmaf_rn(h, __ldg(&W2[jj * 4 + 1]), a1);
        a2 = __fmaf_rn(h, __ldg(&W2[jj * 4 + 2]), a2);
        a3 = __fmaf_rn(h, __ldg(&W2[jj * 4 + 3]), a3);
    }
    a0 = wsum(a0) + __ldg(&b2[0]);
    a1 = wsum(a1) + __ldg(&b2[1]);
    a2 = wsum(a2) + __ldg(&b2[2]);
    a3 = wsum(a3) + __ldg(&b2[3]);
    float mx = fmaxf(fmaxf(a0, a1), fmaxf(a2, a3));
    float e0 = expf(a0 - mx), e1 = expf(a1 - mx), e2 = expf(a2 - mx), e3 = expf(a3 - mx);
    float inv = 1.0f / (e0 + e1 + e2 + e3);
    if (lane < 4) {
        float v = (lane == 0) ? e0 : (lane == 1) ? e1 : (lane == 2) ? e2 : e3;
        g_aw[q * 4 + lane] = v * inv;
    }

    const float* prow = points + (size_t)b * N_ * CIN;
    float4 acc = make_float4(0.f, 0.f, 0.f, 0.f);
    #pragma unroll 4
    for (int k = 0; k < KNNK; ++k) {
        int ik = __shfl_sync(FULLMASK, li, k);
        float4 p = __ldg((const float4*)(prow + (size_t)ik * CIN) + lane);
        acc.x += p.x; acc.y += p.y; acc.z += p.z; acc.w += p.w;
    }
    float4* fr = (float4*)(g_feats + (size_t)q * CIN);
    fr[lane] = make_float4(acc.x * (1.0f / 32.0f), acc.y * (1.0f / 32.0f),
                           acc.z * (1.0f / 32.0f), acc.w * (1.0f / 32.0f));
}

// ---------------- 3) TF32 tensor-core GEMM (unchanged) ---------------------------
constexpr int TBM = 128, TBN = 128, TBK = 32;
constexpr int APAD = 36;
constexpr int BPAD = 136;

__global__ void __launch_bounds__(256) gemm_tc(
    const float* __restrict__ kern, float* __restrict__ out)
{
    __shared__ float As[TBM][APAD];
    __shared__ float Bs[TBK][BPAD];

    int tid  = threadIdx.x;
    int warp = tid >> 5, lane = tid & 31;
    int wm = warp & 1;
    int wn = warp >> 1;
    int gid = lane >> 2, tig = lane & 3;
    int m0 = blockIdx.x * TBM, n0 = blockIdx.y * TBN;

    float acc[4][4][4];
    #pragma unroll
    for (int i = 0; i < 4; ++i)
        #pragma unroll
        for (int j = 0; j < 4; ++j)
            #pragma unroll
            for (int r = 0; r < 4; ++r) acc[i][j][r] = 0.f;

    int arow = tid >> 1, acc0 = (tid & 1) * 16;
    int brow = tid >> 3, bcc0 = (tid & 7) * 16;

    for (int kb = 0; kb < KDIM; kb += TBK) {
        int w  = kb >> 7;
        int c0 = kb & 127;
        {
            float a = __ldg(&g_aw[(m0 + arow) * 4 + w]);
            const float* fp = &g_feats[(size_t)(m0 + arow) * CIN + c0 + acc0];
            #pragma unroll
            for (int u = 0; u < 4; ++u) {
                float4 f = *(const float4*)(fp + u * 4);
                float4 v = make_float4(tf32r(f.x * a), tf32r(f.y * a),
                                       tf32r(f.z * a), tf32r(f.w * a));
                *(float4*)&As[arow][acc0 + u * 4] = v;
            }
        }
        {
            const float* bp = &kern[(size_t)(kb + brow) * COUT + n0 + bcc0];
            #pragma unroll
            for (int u = 0; u < 4; ++u) {
                float4 f = *(const float4*)(bp + u * 4);
                float4 v = make_float4(tf32r(f.x), tf32r(f.y), tf32r(f.z), tf32r(f.w));
                *(float4*)&Bs[brow][bcc0 + u * 4] = v;
            }
        }
        __syncthreads();

        #pragma unroll
        for (int ks = 0; ks < 4; ++ks) {
            uint32_t af[4][4];
            #pragma unroll
            for (int mi = 0; mi < 4; ++mi) {
                int r = wm * 64 + mi * 16;
                int c = ks * 8 + tig;
                af[mi][0] = __float_as_uint(As[r + gid    ][c    ]);
                af[mi][1] = __float_as_uint(As[r + gid + 8][c    ]);
                af[mi][2] = __float_as_uint(As[r + gid    ][c + 4]);
                af[mi][3] = __float_as_uint(As[r + gid + 8][c + 4]);
            }
            uint32_t bf[4][2];
            #pragma unroll
            for (int nj = 0; nj < 4; ++nj) {
                int cb = wn * 32 + nj * 8 + gid;
                bf[nj][0] = __float_as_uint(Bs[ks * 8 + tig    ][cb]);
                bf[nj][1] = __float_as_uint(Bs[ks * 8 + tig + 4][cb]);
            }
            #pragma unroll
            for (int mi = 0; mi < 4; ++mi)
                #pragma unroll
                for (int nj = 0; nj < 4; ++nj)
                    mma_tf32(acc[mi][nj], af[mi], bf[nj]);
        }
        __syncthreads();
    }

    #pragma unroll
    for (int mi = 0; mi < 4; ++mi) {
        #pragma unroll
        for (int nj = 0; nj < 4; ++nj) {
            int r  = m0 + wm * 64 + mi * 16 + gid;
            int cc = n0 + wn * 32 + nj * 8 + 2 * tig;
            *(float2*)&out[(size_t)r * COUT + cc] =
                make_float2(acc[mi][nj][0], acc[mi][nj][1]);
            *(float2*)&out[(size_t)(r + 8) * COUT + cc] =
                make_float2(acc[mi][nj][2], acc[mi][nj][3]);
        }
    }
}

// ---------------- 4) BatchNorm ----------------
__global__ void bn_reduce(const float* __restrict__ out) {
    int o = threadIdx.x;
    size_t r0 = (size_t)blockIdx.x * 64;
    const float* p = out + r0 * COUT + o;
    float s = 0.f, s2 = 0.f;
    #pragma unroll 4
    for (int r = 0; r < 64; ++r) {
        float v = p[(size_t)r * COUT];
        s += v;
        s2 = __fmaf_rn(v, v, s2);
    }
    g_parts[blockIdx.x * COUT + o] = s;
    g_partq[blockIdx.x * COUT + o] = s2;
}

__global__ void bn_final(const float* __restrict__ gamma, const float* __restrict__ beta) {
    int o = threadIdx.x;
    float s = 0.f, s2 = 0.f;
    for (int i = 0; i < 512; ++i) {
        s  += g_parts[i * COUT + o];
        s2 += g_partq[i * COUT + o];
    }
    float mu  = s  * (1.0f / (float)ROWS);
    float var = s2 * (1.0f / (float)ROWS) - mu * mu;
    float sc  = gamma[o] * rsqrtf(var + 1e-5f);
    g_scale[o] = sc;
    g_shift[o] = __fmaf_rn(-mu, sc, beta[o]);
}

__global__ void bn_apply(float* __restrict__ out) {
    int f = blockIdx.x * blockDim.x + threadIdx.x;
    float4 v = ((float4*)out)[f];
    int c4 = f & 63;
    float4 sc = ((const float4*)g_scale)[c4];
    float4 sh = ((const float4*)g_shift)[c4];
    v.x = __fmaf_rn(v.x, sc.x, sh.x);
    v.y = __fmaf_rn(v.y, sc.y, sh.y);
    v.z = __fmaf_rn(v.z, sc.z, sh.z);
    v.w = __fmaf_rn(v.w, sc.w, sh.w);
    ((float4*)out)[f] = v;
}

// ---------------- launch ----------------
extern "C" void kernel_launch(void* const* d_in, const int* in_sizes, int n_in,
                              void* d_out, int out_size)
{
    (void)in_sizes; (void)n_in; (void)out_size;
    const float* xyz    = (const float*)d_in[0];
    const float* points = (const float*)d_in[1];
    const float* W1     = (const float*)d_in[2];
    const float* b1     = (const float*)d_in[3];
    const float* W2     = (const float*)d_in[4];
    const float* b2     = (const float*)d_in[5];
    const float* kern   = (const float*)d_in[6];
    const float* gamma  = (const float*)d_in[7];
    const float* beta   = (const float*)d_in[8];
    float* out = (float*)d_out;

    prep_kernel<<<ROWS / 256, 256>>>(xyz);
    knn_select<<<(ROWS / QPW) * 32 / 256, 256>>>(xyz);
    knn_epilogue<<<ROWS * 32 / 256, 256>>>(points, W1, b1, W2, b2);
    gemm_tc<<<dim3(ROWS / TBM, COUT / TBN), 256>>>(kern, out);
    bn_reduce<<<512, 256>>>(out);
    bn_final<<<1, 256>>>(gamma, beta);
    bn_apply<<<(ROWS * COUT / 4) / 256, 256>>>(out);
}

// round 16
// speedup vs baseline: 1.0331x; 1.0331x over previous
#include <cuda_runtime.h>
#include <cstdint>
#include <cstddef>

#define FULLMASK 0xffffffffu

constexpr int B_   = 4;
constexpr int N_   = 8192;
constexpr int CIN  = 128;
constexpr int COUT = 256;
constexpr int KNNK = 32;
constexpr int NW   = 4;
constexpr int ROWS = B_ * N_;          // 32768
constexpr int KDIM = NW * CIN;         // 512
constexpr int QPW  = 4;                // queries per warp

// ---------------- scratch ----------------
__device__ float4 g_xyzw[ROWS];
__device__ float  g_feats[(size_t)ROWS * CIN];
__device__ float  g_aw[ROWS * NW];
__device__ float  g_parts[512 * COUT];
__device__ float  g_partq[512 * COUT];
__device__ float  g_scale[COUT];
__device__ float  g_shift[COUT];

// ---------------- helpers ----------------
static __device__ __forceinline__ float wsum(float v) {
    #pragma unroll
    for (int o = 16; o > 0; o >>= 1) v += __shfl_xor_sync(FULLMASK, v, o);
    return v;
}

static __device__ __forceinline__ float tf32r(float x) {
    uint32_t u;
    asm("cvt.rna.tf32.f32 %0, %1;" : "=r"(u) : "f"(x));
    return __uint_as_float(u);
}

static __device__ __forceinline__ void mma_tf32(float c[4], const uint32_t a[4],
                                                const uint32_t b[2]) {
    asm volatile(
        "mma.sync.aligned.m16n8k8.row.col.f32.tf32.tf32.f32 "
        "{%0,%1,%2,%3}, {%4,%5,%6,%7}, {%8,%9}, {%0,%1,%2,%3};\n"
        : "+f"(c[0]), "+f"(c[1]), "+f"(c[2]), "+f"(c[3])
        : "r"(a[0]), "r"(a[1]), "r"(a[2]), "r"(a[3]), "r"(b[0]), "r"(b[1]));
}

static __device__ __forceinline__ void cp16(uint32_t dst, const void* src) {
    asm volatile("cp.async.ca.shared.global [%0], [%1], 16;\n" :: "r"(dst), "l"(src));
}

// ---------------- 1) pack xyz + squared norm (CERTIFIED — do not modify) --------
__global__ void prep_kernel(const float* __restrict__ xyz) {
    int gid = blockIdx.x * blockDim.x + threadIdx.x;
    if (gid >= ROWS) return;
    float x = xyz[gid * 3 + 0];
    float y = xyz[gid * 3 + 1];
    float z = xyz[gid * 3 + 2];
    float sq = __fmaf_rn(x, x, __fmaf_rn(y, y, __fmul_rn(z, z)));
    g_xyzw[gid] = make_float4(x, y, z, sq);
}

// ---------------- 2) KNN fused, QPW=4 (best-known R12 structure; CERTIFIED) ------
__global__ void __launch_bounds__(256) knn_kernel(
    const float* __restrict__ points,
    const float* __restrict__ W1, const float* __restrict__ b1,
    const float* __restrict__ W2, const float* __restrict__ b2)
{
    int gw   = (blockIdx.x * blockDim.x + threadIdx.x) >> 5;
    int lane = threadIdx.x & 31;
    int wq   = gw * QPW;
    if (wq >= ROWS) return;
    int b = wq >> 13;

    const float4* cand = g_xyzw + (size_t)b * N_;
    int qbase = wq & (N_ - 1);

    float qx[QPW], qy[QPW], qz[QPW], qs[QPW];
    #pragma unroll
    for (int j = 0; j < QPW; ++j) {
        float4 s = __ldg(&cand[qbase + j]);
        qx[j] = s.x; qy[j] = s.y; qz[j] = s.z; qs[j] = s.w;
    }

    const float INF = __int_as_float(0x7f800000);
    float ld[QPW]  = {INF, INF, INF, INF};
    int   li[QPW]  = {0, 0, 0, 0};
    float tau[QPW] = {INF, INF, INF, INF};

    #pragma unroll 2
    for (int base = 0; base < N_; base += 32) {
        float4 c = __ldg(&cand[base + lane]);
        float d[QPW];
        #pragma unroll
        for (int j = 0; j < QPW; ++j) {
            float dot = __fmul_rn(qx[j], c.x);
            dot = __fmaf_rn(qy[j], c.y, dot);
            dot = __fmaf_rn(qz[j], c.z, dot);
            d[j] = __fadd_rn(__fadd_rn(__fmul_rn(-2.0f, dot), qs[j]), c.w);
        }
        bool hit = (d[0] < tau[0]) | (d[1] < tau[1]) | (d[2] < tau[2]) | (d[3] < tau[3]);
        if (__ballot_sync(FULLMASK, hit)) {
            #pragma unroll
            for (int j = 0; j < QPW; ++j) {
                unsigned m = __ballot_sync(FULLMASK, d[j] < tau[j]);
                while (m) {
                    int src = __ffs(m) - 1;
                    m &= m - 1;
                    float dc = __shfl_sync(FULLMASK, d[j], src);
                    if (dc < tau[j]) {
                        int ic = base + src;
                        unsigned le = __ballot_sync(FULLMASK, ld[j] <= dc);
                        int pos = __popc(le);
                        float pd = __shfl_up_sync(FULLMASK, ld[j], 1);
                        int   pi = __shfl_up_sync(FULLMASK, li[j], 1);
                        if (lane == pos)      { ld[j] = dc; li[j] = ic; }
                        else if (lane > pos)  { ld[j] = pd; li[j] = pi; }
                        tau[j] = __shfl_sync(FULLMASK, ld[j], 31);
                    }
                }
            }
        }
    }

    const float* prow = points + (size_t)b * N_ * CIN;
    #pragma unroll
    for (int j = 0; j < QPW; ++j) {
        float4 nb = cand[li[j]];
        float gx = wsum(__fadd_rn(nb.x, -qx[j])) * (1.0f / 32.0f);
        float gy = wsum(__fadd_rn(nb.y, -qy[j])) * (1.0f / 32.0f);
        float gz = wsum(__fadd_rn(nb.z, -qz[j])) * (1.0f / 32.0f);

        float a0 = 0.f, a1 = 0.f, a2 = 0.f, a3 = 0.f;
        #pragma unroll
        for (int t = 0; t < 2; ++t) {
            int jj = lane + t * 32;
            float h = __ldg(&b1[jj]);
            h = __fmaf_rn(gx, __ldg(&W1[jj]),        h);
            h = __fmaf_rn(gy, __ldg(&W1[64 + jj]),   h);
            h = __fmaf_rn(gz, __ldg(&W1[128 + jj]),  h);
            h = fmaxf(h, 0.0f);
            a0 = __fmaf_rn(h, __ldg(&W2[jj * 4 + 0]), a0);
            a1 = __fmaf_rn(h, __ldg(&W2[jj * 4 + 1]), a1);
            a2 = __fmaf_rn(h, __ldg(&W2[jj * 4 + 2]), a2);
            a3 = __fmaf_rn(h, __ldg(&W2[jj * 4 + 3]), a3);
        }
        a0 = wsum(a0) + __ldg(&b2[0]);
        a1 = wsum(a1) + __ldg(&b2[1]);
        a2 = wsum(a2) + __ldg(&b2[2]);
        a3 = wsum(a3) + __ldg(&b2[3]);
        float mx = fmaxf(fmaxf(a0, a1), fmaxf(a2, a3));
        float e0 = expf(a0 - mx), e1 = expf(a1 - mx), e2 = expf(a2 - mx), e3 = expf(a3 - mx);
        float inv = 1.0f / (e0 + e1 + e2 + e3);
        if (lane < 4) {
            float v = (lane == 0) ? e0 : (lane == 1) ? e1 : (lane == 2) ? e2 : e3;
            g_aw[(wq + j) * 4 + lane] = v * inv;
        }

        float4 acc = make_float4(0.f, 0.f, 0.f, 0.f);
        #pragma unroll 4
        for (int k = 0; k < KNNK; ++k) {
            int ik = __shfl_sync(FULLMASK, li[j], k);
            float4 p = __ldg((const float4*)(prow + (size_t)ik * CIN) + lane);
            acc.x += p.x; acc.y += p.y; acc.z += p.z; acc.w += p.w;
        }
        float4* fr = (float4*)(g_feats + (size_t)(wq + j) * CIN);
        fr[lane] = make_float4(acc.x * (1.0f / 32.0f), acc.y * (1.0f / 32.0f),
                               acc.z * (1.0f / 32.0f), acc.w * (1.0f / 32.0f));
    }
}

// ---------------- 3) TF32 GEMM, cp.async double-buffered --------------------------
constexpr int TBM = 128, TBN = 128, TBK = 32;
constexpr int APAD = 36;                       // A row stride (floats)
constexpr int BPAD = 136;                      // B row stride (floats)
constexpr int ABUF = TBM * APAD;               // 4608 floats
constexpr int BBUF = TBK * BPAD;               // 4352 floats
constexpr int GEMM_SMEM = (2 * ABUF + 2 * BBUF) * 4;   // 71680 bytes

__global__ void __launch_bounds__(256, 2) gemm_tc(
    const float* __restrict__ kern, float* __restrict__ out)
{
    extern __shared__ float smem[];
    float* Abuf[2] = { smem, smem + ABUF };
    float* Bbuf[2] = { smem + 2 * ABUF, smem + 2 * ABUF + BBUF };

    int tid  = threadIdx.x;
    int warp = tid >> 5, lane = tid & 31;
    int wm = warp & 1;
    int wn = warp >> 1;
    int gid = lane >> 2, tig = lane & 3;
    int m0 = blockIdx.x * TBM, n0 = blockIdx.y * TBN;

    // cp.async source/dest mapping
    int arow = tid >> 1, aseg = (tid & 1) * 4;      // A: 2 thr/row, 4×16B each
    int brow = tid >> 3, bseg = (tid & 7) * 4;      // B: 8 thr/row, 4×16B each

    auto prefetch = [&](int it, int buf) {
        int kb = it * TBK;
        int c0 = kb & 127;
        uint32_t ad = (uint32_t)__cvta_generic_to_shared(&Abuf[buf][arow * APAD + aseg * 4]);
        const float* as = &g_feats[(size_t)(m0 + arow) * CIN + c0 + aseg * 4];
        #pragma unroll
        for (int u = 0; u < 4; ++u) cp16(ad + u * 16, as + u * 4);
        uint32_t bd = (uint32_t)__cvta_generic_to_shared(&Bbuf[buf][brow * BPAD + bseg * 4]);
        const float* bs = &kern[(size_t)(kb + brow) * COUT + n0 + bseg * 4];
        #pragma unroll
        for (int u = 0; u < 4; ++u) cp16(bd + u * 16, bs + u * 4);
        asm volatile("cp.async.commit_group;\n");
    };

    float acc[4][4][4];
    #pragma unroll
    for (int i = 0; i < 4; ++i)
        #pragma unroll
        for (int j = 0; j < 4; ++j)
            #pragma unroll
            for (int r = 0; r < 4; ++r) acc[i][j][r] = 0.f;

    constexpr int NIT = KDIM / TBK;   // 16
    prefetch(0, 0);

    for (int it = 0; it < NIT; ++it) {
        int buf = it & 1;
        if (it + 1 < NIT) {
            prefetch(it + 1, buf ^ 1);
            asm volatile("cp.async.wait_group %0;\n" :: "n"(1));
        } else {
            asm volatile("cp.async.wait_group %0;\n" :: "n"(0));
        }
        __syncthreads();

        // aw for this kb's kernel slice (w), per this thread's 8 A-rows
        int w = (it * TBK) >> 7;
        float awv[8];
        #pragma unroll
        for (int mi = 0; mi < 4; ++mi) {
            awv[mi * 2 + 0] = __ldg(&g_aw[(m0 + wm * 64 + mi * 16 + gid    ) * 4 + w]);
            awv[mi * 2 + 1] = __ldg(&g_aw[(m0 + wm * 64 + mi * 16 + gid + 8) * 4 + w]);
        }

        const float* A = Abuf[buf];
        const float* Bm = Bbuf[buf];
        #pragma unroll
        for (int ks = 0; ks < 4; ++ks) {
            uint32_t af[4][4];
            #pragma unroll
            for (int mi = 0; mi < 4; ++mi) {
                int r = wm * 64 + mi * 16;
                int c = ks * 8 + tig;
                af[mi][0] = __float_as_uint(tf32r(__fmul_rn(A[(r + gid    ) * APAD + c    ], awv[mi*2+0])));
                af[mi][1] = __float_as_uint(tf32r(__fmul_rn(A[(r + gid + 8) * APAD + c    ], awv[mi*2+1])));
                af[mi][2] = __float_as_uint(tf32r(__fmul_rn(A[(r + gid    ) * APAD + c + 4], awv[mi*2+0])));
                af[mi][3] = __float_as_uint(tf32r(__fmul_rn(A[(r + gid + 8) * APAD + c + 4], awv[mi*2+1])));
            }
            uint32_t bf[4][2];
            #pragma unroll
            for (int nj = 0; nj < 4; ++nj) {
                int cb = wn * 32 + nj * 8 + gid;
                bf[nj][0] = __float_as_uint(tf32r(Bm[(ks * 8 + tig    ) * BPAD + cb]));
                bf[nj][1] = __float_as_uint(tf32r(Bm[(ks * 8 + tig + 4) * BPAD + cb]));
            }
            #pragma unroll
            for (int mi = 0; mi < 4; ++mi)
                #pragma unroll
                for (int nj = 0; nj < 4; ++nj)
                    mma_tf32(acc[mi][nj], af[mi], bf[nj]);
        }
        __syncthreads();
    }

    #pragma unroll
    for (int mi = 0; mi < 4; ++mi) {
        #pragma unroll
        for (int nj = 0; nj < 4; ++nj) {
            int r  = m0 + wm * 64 + mi * 16 + gid;
            int cc = n0 + wn * 32 + nj * 8 + 2 * tig;
            *(float2*)&out[(size_t)r * COUT + cc] =
                make_float2(acc[mi][nj][0], acc[mi][nj][1]);
            *(float2*)&out[(size_t)(r + 8) * COUT + cc] =
                make_float2(acc[mi][nj][2], acc[mi][nj][3]);
        }
    }
}

// ---------------- 4) BatchNorm ----------------
__global__ void bn_reduce(const float* __restrict__ out) {
    int o = threadIdx.x;
    size_t r0 = (size_t)blockIdx.x * 64;
    const float* p = out + r0 * COUT + o;
    float s = 0.f, s2 = 0.f;
    #pragma unroll 4
    for (int r = 0; r < 64; ++r) {
        float v = p[(size_t)r * COUT];
        s += v;
        s2 = __fmaf_rn(v, v, s2);
    }
    g_parts[blockIdx.x * COUT + o] = s;
    g_partq[blockIdx.x * COUT + o] = s2;
}

__global__ void bn_final(const float* __restrict__ gamma, const float* __restrict__ beta) {
    int o = threadIdx.x;
    float s = 0.f, s2 = 0.f;
    for (int i = 0; i < 512; ++i) {
        s  += g_parts[i * COUT + o];
        s2 += g_partq[i * COUT + o];
    }
    float mu  = s  * (1.0f / (float)ROWS);
    float var = s2 * (1.0f / (float)ROWS) - mu * mu;
    float sc  = gamma[o] * rsqrtf(var + 1e-5f);
    g_scale[o] = sc;
    g_shift[o] = __fmaf_rn(-mu, sc, beta[o]);
}

__global__ void bn_apply(float* __restrict__ out) {
    int f = blockIdx.x * blockDim.x + threadIdx.x;
    float4 v = ((float4*)out)[f];
    int c4 = f & 63;
    float4 sc = ((const float4*)g_scale)[c4];
    float4 sh = ((const float4*)g_shift)[c4];
    v.x = __fmaf_rn(v.x, sc.x, sh.x);
    v.y = __fmaf_rn(v.y, sc.y, sh.y);
    v.z = __fmaf_rn(v.z, sc.z, sh.z);
    v.w = __fmaf_rn(v.w, sc.w, sh.w);
    ((float4*)out)[f] = v;
}

// ---------------- launch ----------------
extern "C" void kernel_launch(void* const* d_in, const int* in_sizes, int n_in,
                              void* d_out, int out_size)
{
    (void)in_sizes; (void)n_in; (void)out_size;
    const float* xyz    = (const float*)d_in[0];
    const float* points = (const float*)d_in[1];
    const float* W1     = (const float*)d_in[2];
    const float* b1     = (const float*)d_in[3];
    const float* W2     = (const float*)d_in[4];
    const float* b2     = (const float*)d_in[5];
    const float* kern   = (const float*)d_in[6];
    const float* gamma  = (const float*)d_in[7];
    const float* beta   = (const float*)d_in[8];
    float* out = (float*)d_out;

    cudaFuncSetAttribute(gemm_tc, cudaFuncAttributeMaxDynamicSharedMemorySize, GEMM_SMEM);

    prep_kernel<<<ROWS / 256, 256>>>(xyz);
    knn_kernel<<<(ROWS / QPW) * 32 / 256, 256>>>(points, W1, b1, W2, b2);
    gemm_tc<<<dim3(ROWS / TBM, COUT / TBN), 256, GEMM_SMEM>>>(kern, out);
    bn_reduce<<<512, 256>>>(out);
    bn_final<<<1, 256>>>(gamma, beta);
    bn_apply<<<(ROWS * COUT / 4) / 256, 256>>>(out);
}